// round 17
// baseline (speedup 1.0000x reference)
#include <cuda_runtime.h>
#include <cuda_fp16.h>
#include <cfloat>
#include <cstdint>
#include <math.h>

#define NROWS   262144
#define DIM     256
#define KCODES  1024
#define NQ      67108864
#define MARGIN  1.0e-2f
#define CB_SCALE 1024.0f
#define DSCALE   0.001953125f        // 2/1024: dist = ee - DSCALE*dot(q(x), q(e*1024))
#define SLOTS   64
#define KEEP    32
#define CANDW   17                   // per-row words in g_cand: [count][16 x packed u16]

// ---------------- scratch (no allocations) ----------------
__device__ float  g_ee[KCODES];
__device__ int    g_counts[KCODES];
__device__ double g_losssum;
__device__ __align__(1024) unsigned char g_cb_q[8 * 32768];  // e4m3 codebook*1024, 8 N-tiles, swizzled
__device__ unsigned g_cand[NROWS * CANDW];

// ---------------- PTX helpers ----------------
__device__ __forceinline__ unsigned smem_u32(const void* p) {
    unsigned a;
    asm("{ .reg .u64 t; cvta.to.shared.u64 t, %1; cvt.u32.u64 %0, t; }" : "=r"(a) : "l"(p));
    return a;
}
#define CP16(dst, src) asm volatile("cp.async.cg.shared.global [%0], [%1], 16;" :: "r"(dst), "l"(src) : "memory")
#define CP_COMMIT()    asm volatile("cp.async.commit_group;" ::: "memory")
#define CP_WAIT0()     asm volatile("cp.async.wait_group 0;" ::: "memory")
#define LDSM4(r, a) \
    asm volatile("ldmatrix.sync.aligned.m8n8.x4.shared.b16 {%0,%1,%2,%3}, [%4];" \
        : "=r"((r)[0]), "=r"((r)[1]), "=r"((r)[2]), "=r"((r)[3]) : "r"(a))

// fp8 e4m3 x e4m3 -> f32 accumulate, K=32
__device__ __forceinline__ void mma_fp8(float* d, const unsigned* a, unsigned b0, unsigned b1) {
    asm volatile("mma.sync.aligned.m16n8k32.row.col.f32.e4m3.e4m3.f32 "
        "{%0,%1,%2,%3}, {%4,%5,%6,%7}, {%8,%9}, {%0,%1,%2,%3};"
        : "+f"(d[0]), "+f"(d[1]), "+f"(d[2]), "+f"(d[3])
        : "r"(a[0]), "r"(a[1]), "r"(a[2]), "r"(a[3]), "r"(b0), "r"(b1));
}

// pack 4 floats into 4 e4m3 bytes (byte0 = f0 ... byte3 = f3)
__device__ __forceinline__ unsigned pack_e4m3(float f0, float f1, float f2, float f3) {
    unsigned short lo, hi;
    asm("cvt.rn.satfinite.e4m3x2.f32 %0, %1, %2;" : "=h"(lo) : "f"(f1), "f"(f0));
    asm("cvt.rn.satfinite.e4m3x2.f32 %0, %1, %2;" : "=h"(hi) : "f"(f3), "f"(f2));
    return (unsigned)lo | ((unsigned)hi << 16);
}

// 8-bit row layout: 256 B per row, 16 chunks of 16B, chunk XOR-swizzled by row&7 (R12-validated).
__device__ __forceinline__ unsigned sw8(int row, int k) {   // k = element idx, mult of 16
    return (unsigned)row * 256u + (unsigned)(((k >> 4) ^ (row & 7)) << 4);
}

// ---------------- kernel 1: exact ee chains + e4m3 swizzled codebook + zero scratch ----------------
__global__ void vq_prep(const float* __restrict__ cb) {
    int gt = blockIdx.x * blockDim.x + threadIdx.x;
    if (gt < KCODES) {
        const float4* p = (const float4*)(cb + (long long)gt * DIM);
        float s = 0.f;
        #pragma unroll 8
        for (int i = 0; i < 64; ++i) {
            float4 v = __ldg(&p[i]);
            s = __fadd_rn(s, __fmul_rn(v.x, v.x));
            s = __fadd_rn(s, __fmul_rn(v.y, v.y));
            s = __fadd_rn(s, __fmul_rn(v.z, v.z));
            s = __fadd_rn(s, __fmul_rn(v.w, v.w));
        }
        g_ee[gt] = s;
        g_counts[gt] = 0;
    }
    if (gt == 0) g_losssum = 0.0;
    for (int i = gt * 16; i < KCODES * DIM; i += gridDim.x * blockDim.x * 16) {
        int code = i >> 8, k = i & 255;
        const float4* p = (const float4*)(cb + i);
        float4 f0 = __ldg(p), f1 = __ldg(p + 1), f2 = __ldg(p + 2), f3 = __ldg(p + 3);
        uint4 w;
        w.x = pack_e4m3(f0.x * CB_SCALE, f0.y * CB_SCALE, f0.z * CB_SCALE, f0.w * CB_SCALE);
        w.y = pack_e4m3(f1.x * CB_SCALE, f1.y * CB_SCALE, f1.z * CB_SCALE, f1.w * CB_SCALE);
        w.z = pack_e4m3(f2.x * CB_SCALE, f2.y * CB_SCALE, f2.z * CB_SCALE, f2.w * CB_SCALE);
        w.w = pack_e4m3(f3.x * CB_SCALE, f3.y * CB_SCALE, f3.z * CB_SCALE, f3.w * CB_SCALE);
        *(uint4*)(g_cb_q + (code >> 7) * 32768 + sw8(code & 127, k)) = w;
    }
}

// ---------------- kernel 2: fp8 e4m3 screening GEMM (k32), 512 threads ----------------
#define EE_OFF    0
#define A_OFF     4096             // 32KB
#define B_OFF     36864            // two 32KB buffers
#define CNT_OFF   102400           // u32[128]
#define CVAL_OFF  102912           // f32[128][64]
#define CIDX_OFF  135680           // u16[128][64]
#define HMIN_OFF  152064           // f32[128][2]
#define SMEM_MMA  153088

__global__ __launch_bounds__(512, 1)
void vq_mma(const float* __restrict__ x) {
    extern __shared__ char smem[];
    const unsigned sb = smem_u32(smem);
    float* ee_s            = (float*)(smem + EE_OFF);
    unsigned* cnt_s        = (unsigned*)(smem + CNT_OFF);
    float* cval_s          = (float*)(smem + CVAL_OFF);
    unsigned short* cidx_s = (unsigned short*)(smem + CIDX_OFF);
    float* hmin_s          = (float*)(smem + HMIN_OFF);
    const int tid = threadIdx.x, wid = tid >> 5, lane = tid & 31;
    const long long row0 = (long long)blockIdx.x * 128;

    if (tid < 128) cnt_s[tid] = 0;
    #pragma unroll
    for (int i = 0; i < 2; ++i) ee_s[tid + i * 512] = g_ee[tid + i * 512];

    // prefetch B tile 0 into buffer 0 (32KB = 2048 chunks)
    #pragma unroll
    for (int j = 0; j < 4; ++j) {
        unsigned off = (unsigned)(tid + j * 512) * 16u;
        CP16(sb + B_OFF + off, (const char*)g_cb_q + off);
    }
    CP_COMMIT();

    // build A: 128 rows x 256 k -> e4m3 swizzled (coalesced ldg, conflict-free sts)
    #pragma unroll
    for (int i = 0; i < 4; ++i) {
        int c = tid + i * 512;                  // 0..2047
        int row = c >> 4, kc = (c & 15) * 16;
        const float4* gp = (const float4*)(x + (row0 + row) * DIM + kc);
        float4 f0 = __ldg(gp), f1 = __ldg(gp + 1), f2 = __ldg(gp + 2), f3 = __ldg(gp + 3);
        uint4 w;
        w.x = pack_e4m3(f0.x, f0.y, f0.z, f0.w);
        w.y = pack_e4m3(f1.x, f1.y, f1.z, f1.w);
        w.z = pack_e4m3(f2.x, f2.y, f2.z, f2.w);
        w.w = pack_e4m3(f3.x, f3.y, f3.z, f3.w);
        *(uint4*)(smem + A_OFF + sw8(row, kc)) = w;
    }

    // warp tiling: 8 row-groups of 16 x 2 col-groups of 64; 16 warps (R12-validated k32 addressing)
    const int mrow0 = (wid >> 1) * 16;
    const int ncol0 = (wid & 1) * 64;
    const int arow  = lane & 15;
    const int akc   = lane >> 4;
    const int bn    = ((lane >> 4) << 3) + (lane & 7);
    const int bkc   = (lane >> 3) & 1;

    float rowmin[2] = {FLT_MAX, FLT_MAX};

    for (int t = 0; t < 8; ++t) {
        CP_WAIT0();
        __syncthreads();
        const unsigned bbuf = sb + B_OFF + (unsigned)(t & 1) * 32768u;
        if (t < 7) {                // prefetch B(t+1) under MMA(t)
            const unsigned nbuf = sb + B_OFF + (unsigned)((t + 1) & 1) * 32768u;
            #pragma unroll
            for (int j = 0; j < 4; ++j) {
                unsigned off = (unsigned)(tid + j * 512) * 16u;
                CP16(nbuf + off, (const char*)g_cb_q + (t + 1) * 32768 + off);
            }
            CP_COMMIT();
        }

        float acc[8][4];
        #pragma unroll
        for (int j = 0; j < 8; ++j)
            #pragma unroll
            for (int q = 0; q < 4; ++q) acc[j][q] = 0.f;

        #pragma unroll
        for (int ks = 0; ks < 8; ++ks) {        // K=32 per step
            unsigned a[4], b[4][4];
            {
                int r = mrow0 + arow;
                LDSM4(a, sb + A_OFF + (unsigned)r * 256u + (unsigned)(((ks * 2 + akc) ^ (r & 7)) << 4));
            }
            #pragma unroll
            for (int nt = 0; nt < 4; ++nt) {
                int n = ncol0 + nt * 16 + bn;
                LDSM4(b[nt], bbuf + (unsigned)n * 256u + (unsigned)(((ks * 2 + bkc) ^ (n & 7)) << 4));
            }
            #pragma unroll
            for (int j = 0; j < 8; ++j)
                mma_fp8(acc[j], a, b[j >> 1][(j & 1) * 2], b[j >> 1][(j & 1) * 2 + 1]);
        }

        // ---- in-register epilogue: distances, row min, candidate push ----
        float facc[8][4];
        #pragma unroll
        for (int j = 0; j < 8; ++j) {
            int cl = ncol0 + j * 8 + (lane & 3) * 2;
            float e0 = ee_s[t * 128 + cl], e1 = ee_s[t * 128 + cl + 1];
            facc[j][0] = fmaf(-DSCALE, acc[j][0], e0);
            facc[j][1] = fmaf(-DSCALE, acc[j][1], e1);
            facc[j][2] = fmaf(-DSCALE, acc[j][2], e0);
            facc[j][3] = fmaf(-DSCALE, acc[j][3], e1);
        }
        #pragma unroll
        for (int h = 0; h < 2; ++h) {
            float m = FLT_MAX;
            #pragma unroll
            for (int j = 0; j < 8; ++j)
                m = fminf(m, fminf(facc[j][h * 2], facc[j][h * 2 + 1]));
            m = fminf(m, __shfl_xor_sync(0xffffffffu, m, 1));   // quad owns row's 64 cols
            m = fminf(m, __shfl_xor_sync(0xffffffffu, m, 2));
            rowmin[h] = fminf(rowmin[h], m);
            const float thr = rowmin[h] + MARGIN;
            const int row = mrow0 + h * 8 + (lane >> 2);
            #pragma unroll
            for (int j = 0; j < 8; ++j)
                #pragma unroll
                for (int q = 0; q < 2; ++q) {
                    float v = facc[j][h * 2 + q];
                    if (v <= thr) {
                        unsigned s = atomicAdd(&cnt_s[row], 1u);
                        if (s < SLOTS) {
                            cval_s[row * SLOTS + s] = v;
                            cidx_s[row * SLOTS + s] =
                                (unsigned short)(t * 128 + ncol0 + j * 8 + (lane & 3) * 2 + q);
                        }
                    }
                }
        }
    }

    // combine col-half minima, final filter, write candidate lists
    if ((lane & 3) == 0) {
        #pragma unroll
        for (int h = 0; h < 2; ++h) {
            int row = mrow0 + h * 8 + (lane >> 2);
            hmin_s[row * 2 + (wid & 1)] = rowmin[h];
        }
    }
    __syncthreads();
    if (tid < 128) {
        float fmin = fminf(hmin_s[tid * 2], hmin_s[tid * 2 + 1]);
        float thr  = fmin + MARGIN;
        unsigned n = cnt_s[tid];
        unsigned short keep[KEEP]; int m = 0; bool ovf = (n > SLOTS);
        if (!ovf) {
            for (unsigned s = 0; s < n; ++s) {
                if (cval_s[tid * SLOTS + s] <= thr) {
                    if (m < KEEP) keep[m++] = cidx_s[tid * SLOTS + s];
                    else { ovf = true; break; }
                }
            }
        }
        unsigned* gc = &g_cand[(row0 + tid) * CANDW];
        gc[0] = ovf ? 255u : (unsigned)m;
        #pragma unroll
        for (int q = 0; q < 16; ++q) {
            unsigned lo = (2 * q     < m) ? (unsigned)keep[2 * q]     : 0u;
            unsigned hi = (2 * q + 1 < m) ? (unsigned)keep[2 * q + 1] : 0u;
            gc[1 + q] = lo | (hi << 16);
        }
    }
}

// ---------------- kernel 3: exact re-rank with m==1 fast path + fused epilogue ----------------
__global__ __launch_bounds__(256)
void vq_exact(const float* __restrict__ x,
              const float* __restrict__ cb,
              float* __restrict__ out) {
    __shared__ float warp_ls[8];
    const int tid = threadIdx.x;
    const long long row = (long long)blockIdx.x * 256 + tid;
    const float4* xr = (const float4*)(x + row * DIM);

    const unsigned* gc = &g_cand[row * CANDW];
    int cnt = (int)__ldg(&gc[0]);
    int sel = 0;

    if (cnt == 1) {
        // single survivor of the screen == provable argmin: no chains needed
        sel = (int)(__ldg(&gc[1]) & 0xFFFFu);
    } else if (cnt != 255) {
        int idxs[KEEP];
        #pragma unroll
        for (int q = 0; q < 16; ++q) {
            unsigned w = __ldg(&gc[1 + q]);
            idxs[2 * q] = (int)(w & 0xFFFFu); idxs[2 * q + 1] = (int)(w >> 16);
        }
        // interleaved exact chains: xx and dot(idxs[0]) — both bit-exact sequential
        const float4* er0 = (const float4*)(cb + (long long)idxs[0] * DIM);
        float xx = 0.f, a0 = 0.f;
        #pragma unroll 8
        for (int i = 0; i < 64; ++i) {
            float4 v = __ldg(&xr[i]);
            float4 e = __ldg(&er0[i]);
            xx = __fadd_rn(xx, __fmul_rn(v.x, v.x)); a0 = fmaf(v.x, e.x, a0);
            xx = __fadd_rn(xx, __fmul_rn(v.y, v.y)); a0 = fmaf(v.y, e.y, a0);
            xx = __fadd_rn(xx, __fmul_rn(v.z, v.z)); a0 = fmaf(v.z, e.z, a0);
            xx = __fadd_rn(xx, __fmul_rn(v.w, v.w)); a0 = fmaf(v.w, e.w, a0);
        }
        float t0 = __fadd_rn(xx, __ldg(&g_ee[idxs[0]]));
        float best = __fadd_rn(t0, __fmul_rn(-2.0f, a0));
        sel = idxs[0];
        for (int c = 1; c < cnt; ++c) {
            int ki = idxs[c];
            const float4* er = (const float4*)(cb + (long long)ki * DIM);
            float a = 0.f;
            #pragma unroll 8
            for (int i = 0; i < 64; ++i) {      // ascending-k exact chain
                float4 v = __ldg(&xr[i]);
                float4 e = __ldg(&er[i]);
                a = fmaf(v.x, e.x, a); a = fmaf(v.y, e.y, a);
                a = fmaf(v.z, e.z, a); a = fmaf(v.w, e.w, a);
            }
            float t = __fadd_rn(xx, __ldg(&g_ee[ki]));
            float d = __fadd_rn(t, __fmul_rn(-2.0f, a));
            if (d < best || (d == best && ki < sel)) { best = d; sel = ki; }  // lowest-idx tie
        }
    } else {                                    // overflow fallback: full exact scan
        float xx = 0.f;
        #pragma unroll 8
        for (int i = 0; i < 64; ++i) {
            float4 v = __ldg(&xr[i]);
            xx = __fadd_rn(xx, __fmul_rn(v.x, v.x));
            xx = __fadd_rn(xx, __fmul_rn(v.y, v.y));
            xx = __fadd_rn(xx, __fmul_rn(v.z, v.z));
            xx = __fadd_rn(xx, __fmul_rn(v.w, v.w));
        }
        float best = FLT_MAX;
        for (int ki = 0; ki < KCODES; ++ki) {
            const float4* er = (const float4*)(cb + (long long)ki * DIM);
            float a = 0.f;
            for (int i = 0; i < 64; ++i) {
                float4 v = __ldg(&xr[i]);
                float4 e = __ldg(&er[i]);
                a = fmaf(v.x, e.x, a); a = fmaf(v.y, e.y, a);
                a = fmaf(v.z, e.z, a); a = fmaf(v.w, e.w, a);
            }
            float t = __fadd_rn(xx, __ldg(&g_ee[ki]));
            float d = __fadd_rn(t, __fmul_rn(-2.0f, a));
            if (d < best) { best = d; sel = ki; }
        }
    }

    // epilogue: gather + straight-through + loss + histogram, vectorized stores
    atomicAdd(&g_counts[sel], 1);
    const float4* qr = (const float4*)(cb + (long long)sel * DIM);
    float4* orow = (float4*)(out + row * DIM);
    float ls = 0.f;
    #pragma unroll 8
    for (int i = 0; i < 64; ++i) {
        float4 xv = __ldg(&xr[i]);
        float4 q  = __ldg(&qr[i]);
        float4 o;
        float d0 = __fadd_rn(q.x, -xv.x); o.x = __fadd_rn(xv.x, d0); ls = fmaf(d0, d0, ls);
        float d1 = __fadd_rn(q.y, -xv.y); o.y = __fadd_rn(xv.y, d1); ls = fmaf(d1, d1, ls);
        float d2 = __fadd_rn(q.z, -xv.z); o.z = __fadd_rn(xv.z, d2); ls = fmaf(d2, d2, ls);
        float d3 = __fadd_rn(q.w, -xv.w); o.w = __fadd_rn(xv.w, d3); ls = fmaf(d3, d3, ls);
        orow[i] = o;
    }
    #pragma unroll
    for (int o = 16; o > 0; o >>= 1) ls += __shfl_xor_sync(0xffffffffu, ls, o);
    if ((tid & 31) == 0) warp_ls[tid >> 5] = ls;
    __syncthreads();
    if (tid == 0) {
        float s = 0.f;
        #pragma unroll
        for (int w = 0; w < 8; ++w) s += warp_ls[w];
        atomicAdd(&g_losssum, (double)s);
    }
}

// ---------------- kernel 4: loss + perplexity ----------------
__global__ void vq_finalize(float* __restrict__ out) {
    __shared__ float sh[1024];
    const int t = threadIdx.x;
    float p = (float)g_counts[t] * (1.0f / (float)NROWS);
    sh[t] = p * logf(p + 1e-10f);
    __syncthreads();
    for (int o = 512; o > 0; o >>= 1) {
        if (t < o) sh[t] += sh[t + o];
        __syncthreads();
    }
    if (t == 0) {
        double mean = g_losssum / (double)NQ;
        float  m    = (float)mean;
        out[NQ]     = __fadd_rn(m, __fmul_rn(0.25f, m));
        out[NQ + 1] = expf(-sh[0]);
    }
}

// ---------------- launch ----------------
extern "C" void kernel_launch(void* const* d_in, const int* in_sizes, int n_in,
                              void* d_out, int out_size) {
    const float* x  = (const float*)d_in[0];
    const float* cb = (const float*)d_in[1];
    float* out = (float*)d_out;

    cudaFuncSetAttribute(vq_mma, cudaFuncAttributeMaxDynamicSharedMemorySize, SMEM_MMA);

    vq_prep<<<256, 256>>>(cb);
    vq_mma<<<NROWS / 128, 512, SMEM_MMA>>>(x);
    vq_exact<<<NROWS / 256, 256>>>(x, cb, out);
    vq_finalize<<<1, 1024>>>(out);
}